// round 4
// baseline (speedup 1.0000x reference)
#include <cuda_runtime.h>

// BiLingual dual EmbeddingBag(sum)
//   inputs_pri: int32 [4096, 200]
//   inputs_sec: int32 [4096, 200]
//   emb_pri:    f32   [100000, 64]   (rows 256B-aligned)
//   emb_sec:    f32   [100000, 64]
//   out:        f32   [2, 4096, 64]
//
// One warp per bag. Half-warp h sums tokens [100*h, 100*h+100); lanes hold a
// float4 dim-quad, so one LDG.128 gathers 2 rows (one per half). Indices
// staged in smem per-warp and consumed as int4 (1 LDS.128 per 4 LDGs).
// Table loads bypass L1 allocation (near-zero reuse at L1).

#define EB_B 4096
#define EB_S 200
#define EB_D 64
#define WPB 8
#define SROW 208                     // padded ints per warp (832B, 16B-aligned)
#define NBLK_PER_TAB (EB_B / WPB)    // 512

__device__ __forceinline__ float4 ldg_na(const float4* p) {
    float4 v;
    asm("ld.global.nc.L1::no_allocate.v4.f32 {%0,%1,%2,%3}, [%4];"
        : "=f"(v.x), "=f"(v.y), "=f"(v.z), "=f"(v.w) : "l"(p));
    return v;
}

__global__ __launch_bounds__(WPB * 32)
void embed_sum_kernel(const int* __restrict__ idx_pri,
                      const int* __restrict__ idx_sec,
                      const float* __restrict__ emb_pri,
                      const float* __restrict__ emb_sec,
                      float* __restrict__ out) {
    __shared__ int sidx[WPB * SROW];

    const int tid  = threadIdx.x;
    const int warp = tid >> 5;
    const int lane = tid & 31;
    const int half = lane >> 4;      // token-range half
    const int hl   = lane & 15;      // dim quad within row

    const int*    idx;
    const float4* tab;
    int           row_base;
    if (blockIdx.x < NBLK_PER_TAB) {
        idx      = idx_pri;
        tab      = reinterpret_cast<const float4*>(emb_pri);
        row_base = blockIdx.x * WPB;
    } else {
        idx      = idx_sec;
        tab      = reinterpret_cast<const float4*>(emb_sec);
        row_base = (blockIdx.x - NBLK_PER_TAB) * WPB;
    }

    // Each warp stages its own bag's 200 indices (coalesced, warp-local).
    {
        const int* gsrc = idx + (row_base + warp) * EB_S;
        #pragma unroll
        for (int i = lane; i < EB_S; i += 32)
            sidx[warp * SROW + i] = gsrc[i];
    }
    __syncwarp();

    // Half h consumes ints [100h, 100h+100) as 25 int4 groups.
    const int4* myv =
        reinterpret_cast<const int4*>(sidx + warp * SROW + half * 100);

    float4 a0 = make_float4(0.f, 0.f, 0.f, 0.f);
    float4 a1 = make_float4(0.f, 0.f, 0.f, 0.f);

    // 24 groups unrolled x2 (8 LDG.128 in flight), then 1 tail group.
    #pragma unroll 2
    for (int g = 0; g < 24; ++g) {
        const int4 id4 = myv[g];
        const float4 v0 = ldg_na(&tab[id4.x * (EB_D / 4) + hl]);
        const float4 v1 = ldg_na(&tab[id4.y * (EB_D / 4) + hl]);
        const float4 v2 = ldg_na(&tab[id4.z * (EB_D / 4) + hl]);
        const float4 v3 = ldg_na(&tab[id4.w * (EB_D / 4) + hl]);
        a0.x += v0.x; a0.y += v0.y; a0.z += v0.z; a0.w += v0.w;
        a1.x += v1.x; a1.y += v1.y; a1.z += v1.z; a1.w += v1.w;
        a0.x += v2.x; a0.y += v2.y; a0.z += v2.z; a0.w += v2.w;
        a1.x += v3.x; a1.y += v3.y; a1.z += v3.z; a1.w += v3.w;
    }
    {
        const int4 id4 = myv[24];
        const float4 v0 = ldg_na(&tab[id4.x * (EB_D / 4) + hl]);
        const float4 v1 = ldg_na(&tab[id4.y * (EB_D / 4) + hl]);
        const float4 v2 = ldg_na(&tab[id4.z * (EB_D / 4) + hl]);
        const float4 v3 = ldg_na(&tab[id4.w * (EB_D / 4) + hl]);
        a0.x += v0.x; a0.y += v0.y; a0.z += v0.z; a0.w += v0.w;
        a1.x += v1.x; a1.y += v1.y; a1.z += v1.z; a1.w += v1.w;
        a0.x += v2.x; a0.y += v2.y; a0.z += v2.z; a0.w += v2.w;
        a1.x += v3.x; a1.y += v3.y; a1.z += v3.z; a1.w += v3.w;
    }

    float4 acc;
    acc.x = a0.x + a1.x;
    acc.y = a0.y + a1.y;
    acc.z = a0.z + a1.z;
    acc.w = a0.w + a1.w;

    // Combine the two token-range halves (lane l <-> lane l^16 hold the
    // same dim quad of the same bag).
    acc.x += __shfl_xor_sync(0xffffffffu, acc.x, 16);
    acc.y += __shfl_xor_sync(0xffffffffu, acc.y, 16);
    acc.z += __shfl_xor_sync(0xffffffffu, acc.z, 16);
    acc.w += __shfl_xor_sync(0xffffffffu, acc.w, 16);

    if (half == 0) {
        const int out_row =
            (blockIdx.x < NBLK_PER_TAB ? 0 : EB_B) + row_base + warp;
        reinterpret_cast<float4*>(out)[out_row * (EB_D / 4) + hl] = acc;
    }
}

extern "C" void kernel_launch(void* const* d_in, const int* in_sizes, int n_in,
                              void* d_out, int out_size) {
    const int*   idx_pri = (const int*)d_in[0];
    const int*   idx_sec = (const int*)d_in[1];
    const float* emb_pri = (const float*)d_in[2];
    const float* emb_sec = (const float*)d_in[3];
    float* outp = (float*)d_out;

    embed_sum_kernel<<<2 * NBLK_PER_TAB, WPB * 32>>>(
        idx_pri, idx_sec, emb_pri, emb_sec, outp);
}

// round 5
// speedup vs baseline: 1.0077x; 1.0077x over previous
#include <cuda_runtime.h>

// BiLingual dual EmbeddingBag(sum)
//   inputs_pri: int32 [4096, 200]
//   inputs_sec: int32 [4096, 200]
//   emb_pri:    f32   [100000, 64]   (rows 256B-aligned)
//   emb_sec:    f32   [100000, 64]
//   out:        f32   [2, 4096, 64]
//
// One warp per bag. Half-warp h sums tokens [100*h, 100*h+100); lanes hold a
// float4 dim-quad, so one LDG.128 gathers 2 rows (one per half). Indices
// staged in smem per-warp and consumed as int4 (1 LDS.128 per 4 LDGs).
// Table loads bypass L1 allocation (near-zero reuse at L1).

#define EB_B 4096
#define EB_S 200
#define EB_D 64
#define WPB 8
#define SROW 208                     // padded ints per warp (832B, 16B-aligned)
#define NBLK_PER_TAB (EB_B / WPB)    // 512

__device__ __forceinline__ float4 ldg_na(const float4* p) {
    float4 v;
    asm("ld.global.nc.L1::no_allocate.v4.f32 {%0,%1,%2,%3}, [%4];"
        : "=f"(v.x), "=f"(v.y), "=f"(v.z), "=f"(v.w) : "l"(p));
    return v;
}

__global__ __launch_bounds__(WPB * 32)
void embed_sum_kernel(const int* __restrict__ idx_pri,
                      const int* __restrict__ idx_sec,
                      const float* __restrict__ emb_pri,
                      const float* __restrict__ emb_sec,
                      float* __restrict__ out) {
    __shared__ int sidx[WPB * SROW];

    const int tid  = threadIdx.x;
    const int warp = tid >> 5;
    const int lane = tid & 31;
    const int half = lane >> 4;      // token-range half
    const int hl   = lane & 15;      // dim quad within row

    const int*    idx;
    const float4* tab;
    int           row_base;
    if (blockIdx.x < NBLK_PER_TAB) {
        idx      = idx_pri;
        tab      = reinterpret_cast<const float4*>(emb_pri);
        row_base = blockIdx.x * WPB;
    } else {
        idx      = idx_sec;
        tab      = reinterpret_cast<const float4*>(emb_sec);
        row_base = (blockIdx.x - NBLK_PER_TAB) * WPB;
    }

    // Each warp stages its own bag's 200 indices (coalesced, warp-local).
    {
        const int* gsrc = idx + (row_base + warp) * EB_S;
        #pragma unroll
        for (int i = lane; i < EB_S; i += 32)
            sidx[warp * SROW + i] = gsrc[i];
    }
    __syncwarp();

    // Half h consumes ints [100h, 100h+100) as 25 int4 groups.
    const int4* myv =
        reinterpret_cast<const int4*>(sidx + warp * SROW + half * 100);

    float4 a0 = make_float4(0.f, 0.f, 0.f, 0.f);
    float4 a1 = make_float4(0.f, 0.f, 0.f, 0.f);

    // 24 groups unrolled x2 (8 LDG.128 in flight), then 1 tail group.
    #pragma unroll 2
    for (int g = 0; g < 24; ++g) {
        const int4 id4 = myv[g];
        const float4 v0 = ldg_na(&tab[id4.x * (EB_D / 4) + hl]);
        const float4 v1 = ldg_na(&tab[id4.y * (EB_D / 4) + hl]);
        const float4 v2 = ldg_na(&tab[id4.z * (EB_D / 4) + hl]);
        const float4 v3 = ldg_na(&tab[id4.w * (EB_D / 4) + hl]);
        a0.x += v0.x; a0.y += v0.y; a0.z += v0.z; a0.w += v0.w;
        a1.x += v1.x; a1.y += v1.y; a1.z += v1.z; a1.w += v1.w;
        a0.x += v2.x; a0.y += v2.y; a0.z += v2.z; a0.w += v2.w;
        a1.x += v3.x; a1.y += v3.y; a1.z += v3.z; a1.w += v3.w;
    }
    {
        const int4 id4 = myv[24];
        const float4 v0 = ldg_na(&tab[id4.x * (EB_D / 4) + hl]);
        const float4 v1 = ldg_na(&tab[id4.y * (EB_D / 4) + hl]);
        const float4 v2 = ldg_na(&tab[id4.z * (EB_D / 4) + hl]);
        const float4 v3 = ldg_na(&tab[id4.w * (EB_D / 4) + hl]);
        a0.x += v0.x; a0.y += v0.y; a0.z += v0.z; a0.w += v0.w;
        a1.x += v1.x; a1.y += v1.y; a1.z += v1.z; a1.w += v1.w;
        a0.x += v2.x; a0.y += v2.y; a0.z += v2.z; a0.w += v2.w;
        a1.x += v3.x; a1.y += v3.y; a1.z += v3.z; a1.w += v3.w;
    }

    float4 acc;
    acc.x = a0.x + a1.x;
    acc.y = a0.y + a1.y;
    acc.z = a0.z + a1.z;
    acc.w = a0.w + a1.w;

    // Combine the two token-range halves (lane l <-> lane l^16 hold the
    // same dim quad of the same bag).
    acc.x += __shfl_xor_sync(0xffffffffu, acc.x, 16);
    acc.y += __shfl_xor_sync(0xffffffffu, acc.y, 16);
    acc.z += __shfl_xor_sync(0xffffffffu, acc.z, 16);
    acc.w += __shfl_xor_sync(0xffffffffu, acc.w, 16);

    if (half == 0) {
        const int out_row =
            (blockIdx.x < NBLK_PER_TAB ? 0 : EB_B) + row_base + warp;
        reinterpret_cast<float4*>(out)[out_row * (EB_D / 4) + hl] = acc;
    }
}

extern "C" void kernel_launch(void* const* d_in, const int* in_sizes, int n_in,
                              void* d_out, int out_size) {
    const int*   idx_pri = (const int*)d_in[0];
    const int*   idx_sec = (const int*)d_in[1];
    const float* emb_pri = (const float*)d_in[2];
    const float* emb_sec = (const float*)d_in[3];
    float* outp = (float*)d_out;

    embed_sum_kernel<<<2 * NBLK_PER_TAB, WPB * 32>>>(
        idx_pri, idx_sec, emb_pri, emb_sec, outp);
}

// round 10
// speedup vs baseline: 1.0087x; 1.0010x over previous
#include <cuda_runtime.h>

// BiLingual dual EmbeddingBag(sum)
//   inputs_pri: int32 [4096, 200]
//   inputs_sec: int32 [4096, 200]
//   emb_pri:    f32   [100000, 64]   (rows 256B-aligned)
//   emb_sec:    f32   [100000, 64]
//   out:        f32   [2, 4096, 64]
//
// One warp per bag. Half-warp h sums tokens [100*h, 100*h+100); lanes hold a
// float4 dim-quad, so one LDG.128 gathers 2 rows (one per half). Indices
// staged in smem per-warp and consumed as int4 (1 LDS.128 per 4 LDGs).
// Table loads bypass L1 allocation (near-zero reuse at L1).

#define EB_B 4096
#define EB_S 200
#define EB_D 64
#define WPB 8
#define SROW 208                     // padded ints per warp (832B, 16B-aligned)
#define NBLK_PER_TAB (EB_B / WPB)    // 512

__device__ __forceinline__ float4 ldg_na(const float4* p) {
    float4 v;
    asm("ld.global.nc.L1::no_allocate.v4.f32 {%0,%1,%2,%3}, [%4];"
        : "=f"(v.x), "=f"(v.y), "=f"(v.z), "=f"(v.w) : "l"(p));
    return v;
}

__global__ __launch_bounds__(WPB * 32)
void embed_sum_kernel(const int* __restrict__ idx_pri,
                      const int* __restrict__ idx_sec,
                      const float* __restrict__ emb_pri,
                      const float* __restrict__ emb_sec,
                      float* __restrict__ out) {
    __shared__ int sidx[WPB * SROW];

    const int tid  = threadIdx.x;
    const int warp = tid >> 5;
    const int lane = tid & 31;
    const int half = lane >> 4;      // token-range half
    const int hl   = lane & 15;      // dim quad within row

    const int*    idx;
    const float4* tab;
    int           row_base;
    if (blockIdx.x < NBLK_PER_TAB) {
        idx      = idx_pri;
        tab      = reinterpret_cast<const float4*>(emb_pri);
        row_base = blockIdx.x * WPB;
    } else {
        idx      = idx_sec;
        tab      = reinterpret_cast<const float4*>(emb_sec);
        row_base = (blockIdx.x - NBLK_PER_TAB) * WPB;
    }

    // Each warp stages its own bag's 200 indices (coalesced, warp-local).
    {
        const int* gsrc = idx + (row_base + warp) * EB_S;
        #pragma unroll
        for (int i = lane; i < EB_S; i += 32)
            sidx[warp * SROW + i] = gsrc[i];
    }
    __syncwarp();

    // Half h consumes ints [100h, 100h+100) as 25 int4 groups.
    const int4* myv =
        reinterpret_cast<const int4*>(sidx + warp * SROW + half * 100);

    float4 a0 = make_float4(0.f, 0.f, 0.f, 0.f);
    float4 a1 = make_float4(0.f, 0.f, 0.f, 0.f);

    // 24 groups unrolled x2 (8 LDG.128 in flight), then 1 tail group.
    #pragma unroll 2
    for (int g = 0; g < 24; ++g) {
        const int4 id4 = myv[g];
        const float4 v0 = ldg_na(&tab[id4.x * (EB_D / 4) + hl]);
        const float4 v1 = ldg_na(&tab[id4.y * (EB_D / 4) + hl]);
        const float4 v2 = ldg_na(&tab[id4.z * (EB_D / 4) + hl]);
        const float4 v3 = ldg_na(&tab[id4.w * (EB_D / 4) + hl]);
        a0.x += v0.x; a0.y += v0.y; a0.z += v0.z; a0.w += v0.w;
        a1.x += v1.x; a1.y += v1.y; a1.z += v1.z; a1.w += v1.w;
        a0.x += v2.x; a0.y += v2.y; a0.z += v2.z; a0.w += v2.w;
        a1.x += v3.x; a1.y += v3.y; a1.z += v3.z; a1.w += v3.w;
    }
    {
        const int4 id4 = myv[24];
        const float4 v0 = ldg_na(&tab[id4.x * (EB_D / 4) + hl]);
        const float4 v1 = ldg_na(&tab[id4.y * (EB_D / 4) + hl]);
        const float4 v2 = ldg_na(&tab[id4.z * (EB_D / 4) + hl]);
        const float4 v3 = ldg_na(&tab[id4.w * (EB_D / 4) + hl]);
        a0.x += v0.x; a0.y += v0.y; a0.z += v0.z; a0.w += v0.w;
        a1.x += v1.x; a1.y += v1.y; a1.z += v1.z; a1.w += v1.w;
        a0.x += v2.x; a0.y += v2.y; a0.z += v2.z; a0.w += v2.w;
        a1.x += v3.x; a1.y += v3.y; a1.z += v3.z; a1.w += v3.w;
    }

    float4 acc;
    acc.x = a0.x + a1.x;
    acc.y = a0.y + a1.y;
    acc.z = a0.z + a1.z;
    acc.w = a0.w + a1.w;

    // Combine the two token-range halves (lane l <-> lane l^16 hold the
    // same dim quad of the same bag).
    acc.x += __shfl_xor_sync(0xffffffffu, acc.x, 16);
    acc.y += __shfl_xor_sync(0xffffffffu, acc.y, 16);
    acc.z += __shfl_xor_sync(0xffffffffu, acc.z, 16);
    acc.w += __shfl_xor_sync(0xffffffffu, acc.w, 16);

    if (half == 0) {
        const int out_row =
            (blockIdx.x < NBLK_PER_TAB ? 0 : EB_B) + row_base + warp;
        reinterpret_cast<float4*>(out)[out_row * (EB_D / 4) + hl] = acc;
    }
}

extern "C" void kernel_launch(void* const* d_in, const int* in_sizes, int n_in,
                              void* d_out, int out_size) {
    const int*   idx_pri = (const int*)d_in[0];
    const int*   idx_sec = (const int*)d_in[1];
    const float* emb_pri = (const float*)d_in[2];
    const float* emb_sec = (const float*)d_in[3];
    float* outp = (float*)d_out;

    embed_sum_kernel<<<2 * NBLK_PER_TAB, WPB * 32>>>(
        idx_pri, idx_sec, emb_pri, emb_sec, outp);
}

// round 11
// speedup vs baseline: 1.2257x; 1.2152x over previous
#include <cuda_runtime.h>

// BiLingual dual EmbeddingBag(sum)
//   inputs_pri: int32 [4096, 200]
//   inputs_sec: int32 [4096, 200]
//   emb_pri:    f32   [100000, 64]   (rows 256B)
//   emb_sec:    f32   [100000, 64]
//   out:        f32   [2, 4096, 64]
//
// R2 structure (best known: 25.1us): one warp per bag, half-warp h loads
// token j+h as float4 (one LDG.128 covers 2 tokens), indices staged in smem.
// R4 change: unroll 8 (8 LDG.128 in flight) + split accumulators.
// Loads stay L1-allocating (__ldg) — L1 hits carry ~1/3 of traffic.

#define EB_B 4096
#define EB_S 200
#define EB_D 64
#define WPB 8
#define NBLK_PER_TAB (EB_B / WPB)   // 512

__global__ __launch_bounds__(WPB * 32)
void embed_sum_kernel(const int* __restrict__ idx_pri,
                      const int* __restrict__ idx_sec,
                      const float* __restrict__ emb_pri,
                      const float* __restrict__ emb_sec,
                      float* __restrict__ out) {
    __shared__ int sidx[WPB * EB_S];

    const int tid  = threadIdx.x;
    const int warp = tid >> 5;
    const int lane = tid & 31;
    const int half = lane >> 4;     // which token of the pair
    const int hl   = lane & 15;     // dim quad within row

    const int*    idx;
    const float4* tab;
    int           row_base;
    if (blockIdx.x < NBLK_PER_TAB) {
        idx      = idx_pri;
        tab      = reinterpret_cast<const float4*>(emb_pri);
        row_base = blockIdx.x * WPB;
    } else {
        idx      = idx_sec;
        tab      = reinterpret_cast<const float4*>(emb_sec);
        row_base = (blockIdx.x - NBLK_PER_TAB) * WPB;
    }

    // Stage this block's 8x200 indices (coalesced).
    {
        const int* gsrc = idx + row_base * EB_S;
        #pragma unroll
        for (int i = tid; i < WPB * EB_S; i += WPB * 32)
            sidx[i] = gsrc[i];
    }
    __syncthreads();

    const int* my = &sidx[warp * EB_S];

    float4 a0 = make_float4(0.f, 0.f, 0.f, 0.f);
    float4 a1 = make_float4(0.f, 0.f, 0.f, 0.f);

    // 96 pair-iterations unrolled x8 (8 LDG.128 in flight), then 4 tail.
    #pragma unroll 1
    for (int g = 0; g < 96; g += 8) {
        // Gather the 8 indices for this batch first, then issue all 8 LDGs.
        int ids[8];
        #pragma unroll
        for (int u = 0; u < 8; ++u)
            ids[u] = my[2 * (g + u) + half];

        float4 v[8];
        #pragma unroll
        for (int u = 0; u < 8; ++u)
            v[u] = __ldg(&tab[ids[u] * (EB_D / 4) + hl]);

        #pragma unroll
        for (int u = 0; u < 8; u += 2) {
            a0.x += v[u].x;     a0.y += v[u].y;
            a0.z += v[u].z;     a0.w += v[u].w;
            a1.x += v[u + 1].x; a1.y += v[u + 1].y;
            a1.z += v[u + 1].z; a1.w += v[u + 1].w;
        }
    }
    // Tail: pair-iterations 96..99 (tokens 192..199).
    {
        int ids[4];
        #pragma unroll
        for (int u = 0; u < 4; ++u)
            ids[u] = my[2 * (96 + u) + half];

        float4 v[4];
        #pragma unroll
        for (int u = 0; u < 4; ++u)
            v[u] = __ldg(&tab[ids[u] * (EB_D / 4) + hl]);

        #pragma unroll
        for (int u = 0; u < 4; u += 2) {
            a0.x += v[u].x;     a0.y += v[u].y;
            a0.z += v[u].z;     a0.w += v[u].w;
            a1.x += v[u + 1].x; a1.y += v[u + 1].y;
            a1.z += v[u + 1].z; a1.w += v[u + 1].w;
        }
    }

    float4 acc;
    acc.x = a0.x + a1.x;
    acc.y = a0.y + a1.y;
    acc.z = a0.z + a1.z;
    acc.w = a0.w + a1.w;

    // Combine the two half-warp partials (same bag, same dim quad).
    acc.x += __shfl_xor_sync(0xffffffffu, acc.x, 16);
    acc.y += __shfl_xor_sync(0xffffffffu, acc.y, 16);
    acc.z += __shfl_xor_sync(0xffffffffu, acc.z, 16);
    acc.w += __shfl_xor_sync(0xffffffffu, acc.w, 16);

    if (half == 0) {
        const int out_row =
            (blockIdx.x < NBLK_PER_TAB ? 0 : EB_B) + row_base + warp;
        reinterpret_cast<float4*>(out)[out_row * (EB_D / 4) + hl] = acc;
    }
}

extern "C" void kernel_launch(void* const* d_in, const int* in_sizes, int n_in,
                              void* d_out, int out_size) {
    const int*   idx_pri = (const int*)d_in[0];
    const int*   idx_sec = (const int*)d_in[1];
    const float* emb_pri = (const float*)d_in[2];
    const float* emb_sec = (const float*)d_in[3];
    float* outp = (float*)d_out;

    embed_sum_kernel<<<2 * NBLK_PER_TAB, WPB * 32>>>(
        idx_pri, idx_sec, emb_pri, emb_sec, outp);
}